// round 17
// baseline (speedup 1.0000x reference)
#include <cuda_runtime.h>
#include <cstdint>

#define NN   384
#define HH   128
#define LATD 64
#define RR   16
#define LL   3
#define TT   64
#define MSs  132     // tile row stride (528B = 33*16)
#define RBs  20      // rbf tile row stride
#define RBB  16
#define CUT2 144.0f
#define GAMMA 1.7777778f   // (16/12)^2
#define MUSTEP 0.8f        // 12/15

typedef unsigned long long u64;

// ---------------- device scratch ----------------
__device__ float g_h[NN * HH];
__device__ float g_x[NN * 3];
__device__ float g_agg[NN * HH];
__device__ float g_base1[NN * HH];
__device__ float g_t1[NN * HH];
__device__ int   g_nbr[NN * NN];
__device__ float g_dist[NN * NN];
__device__ float g_dvec[NN * NN * 3];
__device__ int   g_cnt[NN];
__device__ int   g_order[NN];          // LPT schedule (cnt descending)

__device__ __forceinline__ float silu_f(float v) {
    return __fdividef(v, 1.0f + __expf(-v));
}
__device__ __forceinline__ u64 pk2(float x, float y) {
    u64 r; asm("mov.b64 %0,{%1,%2};" : "=l"(r) : "f"(x), "f"(y)); return r;
}
__device__ __forceinline__ u64 fma2(u64 a, u64 b, u64 c) {
    u64 d; asm("fma.rn.f32x2 %0,%1,%2,%3;" : "=l"(d) : "l"(a), "l"(b), "l"(c)); return d;
}
__device__ __forceinline__ float2 upk(u64 a) {
    float2 f; asm("mov.b64 {%0,%1},%2;" : "=f"(f.x), "=f"(f.y) : "l"(a)); return f;
}
__device__ __forceinline__ void cpa16(float* s, const float* g) {
    unsigned sa = (unsigned)__cvta_generic_to_shared(s);
    asm volatile("cp.async.cg.shared.global [%0], [%1], 16;" :: "r"(sa), "l"(g));
}
__device__ __forceinline__ void cpa_commit() { asm volatile("cp.async.commit_group;"); }
template <int W> __device__ __forceinline__ void cpa_wait() {
    asm volatile("cp.async.wait_group %0;" :: "n"(W) : "memory");
}
__device__ __forceinline__ void stage_async(float* dst, const float* src, int nfl, int tid) {
    for (int i = tid * 4; i < nfl; i += 1024) cpa16(dst + i, src + i);
}

// ---------------- init: proj (blocks 0..383) + center (block 384) ----------------
__global__ void k_init(const float* __restrict__ z, const float* __restrict__ W,
                       const float* __restrict__ b, const float* __restrict__ anchor) {
    if (blockIdx.x < NN) {
        __shared__ float zr[LATD];
        int i = blockIdx.x, c = threadIdx.x;
        if (c < LATD) zr[c] = z[i * LATD + c];
        __syncthreads();
        float acc = b[c];
#pragma unroll 8
        for (int k = 0; k < LATD; k++) acc = fmaf(zr[k], W[k * HH + c], acc);
        g_h[i * HH + c] = acc;
    } else {
        __shared__ float part[128][3];
        __shared__ float mean[3];
        int t = threadIdx.x;
        float s0 = 0.f, s1 = 0.f, s2 = 0.f;
        for (int j = t; j < NN; j += 128) {
            s0 += anchor[j * 3 + 0]; s1 += anchor[j * 3 + 1]; s2 += anchor[j * 3 + 2];
        }
        part[t][0] = s0; part[t][1] = s1; part[t][2] = s2;
        __syncthreads();
        if (t < 3) {
            float s = 0.f;
            for (int q = 0; q < 128; q++) s += part[q][t];
            mean[t] = s / (float)NN;
        }
        __syncthreads();
        for (int j = t; j < NN; j += 128) {
            g_x[j * 3 + 0] = anchor[j * 3 + 0] - mean[0];
            g_x[j * 3 + 1] = anchor[j * 3 + 1] - mean[1];
            g_x[j * 3 + 2] = anchor[j * 3 + 2] - mean[2];
        }
    }
}

// ---------------- k_sched: stable rank sort by cnt descending (perf-only) ----------------
__global__ void k_sched() {
    __shared__ int keys[NN];
    int tid = threadIdx.x;
    keys[tid] = g_cnt[tid];
    __syncthreads();
    int k = keys[tid];
    int pos = 0;
#pragma unroll 8
    for (int q = 0; q < NN; q++) {
        int kq = keys[q];
        pos += (kq > k) || (kq == k && q < tid);
    }
    g_order[pos] = tid;
}

// ---------------- single-row f32x2 GEMM helper (K=128, smem weights) ----------------
__device__ __forceinline__ void gemm_row128(u64 acc[4], const float* __restrict__ u0,
                                            const float* __restrict__ w, int cg) {
#pragma unroll 4
    for (int k = 0; k < HH; k += 2) {
        ulonglong2 w0a = *(const ulonglong2*)(w + k * HH + cg);
        ulonglong2 w0b = *(const ulonglong2*)(w + k * HH + cg + 4);
        ulonglong2 w1a = *(const ulonglong2*)(w + (k + 1) * HH + cg);
        ulonglong2 w1b = *(const ulonglong2*)(w + (k + 1) * HH + cg + 4);
        float2 uv = *(const float2*)(u0 + k);
        u64 ua = pk2(uv.x, uv.x), ub = pk2(uv.y, uv.y);
        acc[0] = fma2(ua, w0a.x, acc[0]); acc[1] = fma2(ua, w0a.y, acc[1]);
        acc[2] = fma2(ua, w0b.x, acc[2]); acc[3] = fma2(ua, w0b.y, acc[3]);
        acc[0] = fma2(ub, w1a.x, acc[0]); acc[1] = fma2(ub, w1a.y, acc[1]);
        acc[2] = fma2(ub, w1b.x, acc[2]); acc[3] = fma2(ub, w1b.y, acc[3]);
    }
}
__device__ __forceinline__ void store_row8(float* d, const u64 acc[4]) {
    float2 t; float4 o0, o1;
    t = upk(acc[0]); o0.x = t.x; o0.y = t.y;
    t = upk(acc[1]); o0.z = t.x; o0.w = t.y;
    t = upk(acc[2]); o1.x = t.x; o1.y = t.y;
    t = upk(acc[3]); o1.z = t.x; o1.w = t.y;
    *(float4*)d = o0; *(float4*)(d + 4) = o1;
}

// ---------------- k_prep: graph (blocks<NN) + [node-update] + base1/t1 (blocks>=NN) ----------------
#define SB_PREP ((2 * HH * HH + 3 * RBB * HH + 3 * HH) * 4)
__global__ __launch_bounds__(256, 1) void k_prep(
    const float* __restrict__ eW1, const float* __restrict__ eb1,
    const float* __restrict__ nW1, const float* __restrict__ nb1,
    const float* __restrict__ nW2, const float* __restrict__ nb2,
    int l, int do_node) {
    extern __shared__ float sb[];
    const int tid = threadIdx.x;
    if (blockIdx.x < NN) {
        int* wcnt  = (int*)sb;
        int* wbase = wcnt + 8;
        int* totalp = wbase + 8;
        const int r = blockIdx.x;
        const int lane = tid & 31, w = tid >> 5;
        const float xi0 = g_x[r * 3 + 0], xi1 = g_x[r * 3 + 1], xi2 = g_x[r * 3 + 2];
        if (tid == 0) *totalp = 0;
        __syncthreads();
        for (int base = 0; base < NN; base += 256) {
            int j = base + tid;
            bool p = false;
            float dx = 0.f, dy = 0.f, dz = 0.f, d2 = 0.f;
            if (j < NN && j != r) {
                dx = xi0 - g_x[j * 3 + 0];
                dy = xi1 - g_x[j * 3 + 1];
                dz = xi2 - g_x[j * 3 + 2];
                d2 = dx * dx + dy * dy + dz * dz;
                p = (d2 < CUT2) || (j == r - 1) || (j == r + 1);
            }
            unsigned bal = __ballot_sync(0xffffffffu, p);
            if (lane == 0) wcnt[w] = __popc(bal);
            __syncthreads();
            if (tid == 0) {
                int run = *totalp;
                for (int q = 0; q < 8; q++) { wbase[q] = run; run += wcnt[q]; }
                *totalp = run;
            }
            __syncthreads();
            if (p) {
                int pos = wbase[w] + __popc(bal & ((1u << lane) - 1u));
                g_nbr[r * NN + pos] = j;
                g_dist[r * NN + pos] = sqrtf(d2);
                g_dvec[(r * NN + pos) * 3 + 0] = dx;
                g_dvec[(r * NN + pos) * 3 + 1] = dy;
                g_dvec[(r * NN + pos) * 3 + 2] = dz;
            }
            __syncthreads();
        }
        if (tid == 0) g_cnt[r] = *totalp;
    } else {
        float* ws  = sb;                  // HH*HH  (ping)
        float* ws2 = ws + HH * HH;        // HH*HH  (pong)
        float* hs  = ws2 + HH * HH;       // RBB*HH
        float* as_ = hs + RBB * HH;       // RBB*HH
        float* n1s = as_ + RBB * HH;      // RBB*HH
        float* bs  = n1s + RBB * HH;      // HH (eb1)
        float* b1s = bs + HH;             // HH (nb1)
        float* b2s = b1s + HH;            // HH (nb2)
        const int r0 = (blockIdx.x - NN) * RBB;
        const int r = tid >> 4, cg = (tid & 15) * 8;
        const float* We = eW1 + (size_t)l * 272 * HH;

        if (do_node) {
            const float* W1 = nW1 + (size_t)(l - 1) * 2 * HH * HH;
            const float* W2 = nW2 + (size_t)(l - 1) * HH * HH;
            stage_async(ws, W1, HH * HH, tid);            // G0: W1 h-part
            cpa_commit();
            stage_async(ws2, W1 + HH * HH, HH * HH, tid); // G1: W1 agg-part
            cpa_commit();
            for (int idx = tid; idx < RBB * HH / 4; idx += 256) {
                *(float4*)(hs + idx * 4)  = *(const float4*)(g_h + r0 * HH + idx * 4);
                *(float4*)(as_ + idx * 4) = *(const float4*)(g_agg + r0 * HH + idx * 4);
            }
            if (tid < HH) {
                bs[tid]  = eb1[l * HH + tid];
                b1s[tid] = nb1[(l - 1) * HH + tid];
                b2s[tid] = nb2[(l - 1) * HH + tid];
            }
            cpa_wait<1>();          // G0 done
            __syncthreads();

            u64 accN[4] = {0ull, 0ull, 0ull, 0ull};
            gemm_row128(accN, hs + r * HH, ws, cg);       // h @ W1h
            __syncthreads();                               // ws free
            stage_async(ws, W2, HH * HH, tid);             // G2: W2
            cpa_commit();
            cpa_wait<1>();          // G1 done
            __syncthreads();
            gemm_row128(accN, as_ + r * HH, ws2, cg);     // + agg @ W1a
            __syncthreads();                               // ws2 free
            stage_async(ws2, We, HH * HH, tid);            // G3: eW1 lo
            cpa_commit();
            {   // n1 = silu(accN + b1)
                float2 t0 = upk(accN[0]), t1 = upk(accN[1]);
                float2 t2 = upk(accN[2]), t3 = upk(accN[3]);
                float* d = n1s + r * HH + cg;
                d[0] = silu_f(t0.x + b1s[cg + 0]); d[1] = silu_f(t0.y + b1s[cg + 1]);
                d[2] = silu_f(t1.x + b1s[cg + 2]); d[3] = silu_f(t1.y + b1s[cg + 3]);
                d[4] = silu_f(t2.x + b1s[cg + 4]); d[5] = silu_f(t2.y + b1s[cg + 5]);
                d[6] = silu_f(t3.x + b1s[cg + 6]); d[7] = silu_f(t3.y + b1s[cg + 7]);
            }
            cpa_wait<1>();          // G2 done
            __syncthreads();        // n1s visible; ws = W2
            u64 accH[4] = {0ull, 0ull, 0ull, 0ull};
            gemm_row128(accH, n1s + r * HH, ws, cg);      // n1 @ W2
            __syncthreads();                               // ws free
            stage_async(ws, We + HH * HH, HH * HH, tid);   // G4: eW1 hi
            cpa_commit();
            {   // h_new = h + b2 + accH -> hs and g_h
                float2 t0 = upk(accH[0]), t1 = upk(accH[1]);
                float2 t2 = upk(accH[2]), t3 = upk(accH[3]);
                float* hp = hs + r * HH + cg;
                float v0 = hp[0] + b2s[cg + 0] + t0.x, v1 = hp[1] + b2s[cg + 1] + t0.y;
                float v2 = hp[2] + b2s[cg + 2] + t1.x, v3 = hp[3] + b2s[cg + 3] + t1.y;
                float v4 = hp[4] + b2s[cg + 4] + t2.x, v5 = hp[5] + b2s[cg + 5] + t2.y;
                float v6 = hp[6] + b2s[cg + 6] + t3.x, v7 = hp[7] + b2s[cg + 7] + t3.y;
                hp[0] = v0; hp[1] = v1; hp[2] = v2; hp[3] = v3;
                hp[4] = v4; hp[5] = v5; hp[6] = v6; hp[7] = v7;
                float* gp = g_h + (r0 + r) * HH + cg;
                gp[0] = v0; gp[1] = v1; gp[2] = v2; gp[3] = v3;
                gp[4] = v4; gp[5] = v5; gp[6] = v6; gp[7] = v7;
            }
            cpa_wait<1>();          // G3 done (eW1 lo in ws2)
            __syncthreads();        // hs updated, visible
            {
                const u64* bp = (const u64*)(bs + cg);
                u64 acc[4] = {bp[0], bp[1], bp[2], bp[3]};
                gemm_row128(acc, hs + r * HH, ws2, cg);
                store_row8(g_base1 + (r0 + r) * HH + cg, acc);
            }
            cpa_wait<0>();          // G4 done (eW1 hi in ws)
            __syncthreads();
            {
                u64 acc[4] = {0ull, 0ull, 0ull, 0ull};
                gemm_row128(acc, hs + r * HH, ws, cg);
                store_row8(g_t1 + (r0 + r) * HH + cg, acc);
            }
        } else {
            stage_async(ws, We, HH * HH, tid);             // G0: eW1 lo
            cpa_commit();
            stage_async(ws2, We + HH * HH, HH * HH, tid);  // G1: eW1 hi
            cpa_commit();
            for (int idx = tid; idx < RBB * HH / 4; idx += 256)
                *(float4*)(hs + idx * 4) = *(const float4*)(g_h + r0 * HH + idx * 4);
            if (tid < HH) bs[tid] = eb1[l * HH + tid];
            cpa_wait<1>();
            __syncthreads();
            {
                const u64* bp = (const u64*)(bs + cg);
                u64 acc[4] = {bp[0], bp[1], bp[2], bp[3]};
                gemm_row128(acc, hs + r * HH, ws, cg);
                store_row8(g_base1 + (r0 + r) * HH + cg, acc);
            }
            cpa_wait<0>();
            __syncthreads();
            {
                u64 acc[4] = {0ull, 0ull, 0ull, 0ull};
                gemm_row128(acc, hs + r * HH, ws2, cg);
                store_row8(g_t1 + (r0 + r) * HH + cg, acc);
            }
        }
    }
}

// ---------------- tile GEMM: warp-per-k-row, 8j x 4c, chunk-4 float4 u loads ----------------
template <int K>
__device__ __forceinline__ void gemmT(const float* __restrict__ u, int ustr,
                                      const float* __restrict__ w,
                                      const float* __restrict__ bias,
                                      float* __restrict__ dst, int dstr,
                                      int tid, int tc) {
    const int wq = tid >> 5, lane = tid & 31;
    const int jr = wq << 3;
    if (jr >= tc) return;
    const int c4 = lane * 4;
    u64 acc[8][2];
    {
        ulonglong2 b = *(const ulonglong2*)(bias + c4);
#pragma unroll
        for (int jj = 0; jj < 8; jj++) { acc[jj][0] = b.x; acc[jj][1] = b.y; }
    }
    const float* u0 = u + jr * ustr;
#pragma unroll 2
    for (int k = 0; k < K; k += 4) {
        ulonglong2 w0 = *(const ulonglong2*)(w + (k + 0) * HH + c4);
        ulonglong2 w1 = *(const ulonglong2*)(w + (k + 1) * HH + c4);
        ulonglong2 w2 = *(const ulonglong2*)(w + (k + 2) * HH + c4);
        ulonglong2 w3 = *(const ulonglong2*)(w + (k + 3) * HH + c4);
#pragma unroll
        for (int jj = 0; jj < 8; jj++) {
            float4 uv = *(const float4*)(u0 + jj * ustr + k);
            u64 a0 = pk2(uv.x, uv.x), a1 = pk2(uv.y, uv.y);
            u64 a2 = pk2(uv.z, uv.z), a3 = pk2(uv.w, uv.w);
            acc[jj][0] = fma2(a0, w0.x, acc[jj][0]);
            acc[jj][1] = fma2(a0, w0.y, acc[jj][1]);
            acc[jj][0] = fma2(a1, w1.x, acc[jj][0]);
            acc[jj][1] = fma2(a1, w1.y, acc[jj][1]);
            acc[jj][0] = fma2(a2, w2.x, acc[jj][0]);
            acc[jj][1] = fma2(a2, w2.y, acc[jj][1]);
            acc[jj][0] = fma2(a3, w3.x, acc[jj][0]);
            acc[jj][1] = fma2(a3, w3.y, acc[jj][1]);
        }
    }
#pragma unroll
    for (int jj = 0; jj < 8; jj++) {
        float2 t0 = upk(acc[jj][0]), t1 = upk(acc[jj][1]);
        float4 o;
        o.x = silu_f(t0.x); o.y = silu_f(t0.y);
        o.z = silu_f(t1.x); o.w = silu_f(t1.y);
        *(float4*)(dst + (jr + jj) * dstr + c4) = o;
    }
}

// ---------------- edge kernel: one CTA per receiver, LPT order, fused x-update ----------------
#define SM_FLOATS (16*HH + HH*HH + HH*HH + TT*MSs + TT*MSs + TT*RBs + 5*HH + 256 + TT*3 + 4)
#define SMEM_EDGE (SM_FLOATS * 4)

__global__ __launch_bounds__(256, 1) void k_edge(
    const float* __restrict__ eW1, const float* __restrict__ eW2,
    const float* __restrict__ eb2, const float* __restrict__ cW1,
    const float* __restrict__ cb1, const float* __restrict__ cW2,
    float* __restrict__ out, int l, int last) {
    extern __shared__ float sm[];
    float* wrbf  = sm;                   // 16*HH
    float* wb2   = wrbf + 16 * HH;       // HH*HH  (eW2)
    float* wb3   = wb2 + HH * HH;        // HH*HH  (cW1)
    float* m1s   = wb3 + HH * HH;        // TT*MSs
    float* ms    = m1s + TT * MSs;       // TT*MSs
    float* rbfs  = ms + TT * MSs;        // TT*RBs
    float* base1 = rbfs + TT * RBs;      // HH
    float* eb2s  = base1 + HH;           // HH
    float* cb1s  = eb2s + HH;            // HH
    float* cW2s  = cb1s + HH;            // HH
    float* aggs  = cW2s + HH;            // HH
    float* part2 = aggs + HH;            // 256
    float* cont  = part2 + 256;          // TT*3
    float* xacc  = cont + TT * 3;        // 4

    const int r = g_order[blockIdx.x];   // LPT schedule
    const int tid = threadIdx.x;
    const int wq = tid >> 5, lane = tid & 31;

    stage_async(wrbf, eW1 + ((size_t)l * 272 + 256) * HH, 16 * HH, tid);
    stage_async(wb2, eW2 + (size_t)l * HH * HH, HH * HH, tid);
    stage_async(wb3, cW1 + (size_t)l * HH * HH, HH * HH, tid);
    cpa_commit();

    if (tid < HH) {
        base1[tid] = g_base1[r * HH + tid];
        eb2s[tid]  = eb2[l * HH + tid];
        cb1s[tid]  = cb1[l * HH + tid];
        cW2s[tid]  = cW2[l * HH + tid];
        aggs[tid]  = 0.f;
    }
    if (tid < 3) xacc[tid] = 0.f;
    const int cnt = g_cnt[r];

    for (int t0 = 0; t0 < cnt; t0 += TT) {
        const int tc = min(TT, cnt - t0);
        const int tcr8 = (tc + 7) & ~7;

        for (int idx = tid; idx < tcr8 * 32; idx += 256) {
            int jj = idx >> 5, c16 = (idx & 31) * 4;
            if (jj < tc) {
                int j = g_nbr[r * NN + t0 + jj];
                cpa16(m1s + jj * MSs + c16, g_t1 + j * HH + c16);
            } else {
                *(float4*)(m1s + jj * MSs + c16) = make_float4(0.f, 0.f, 0.f, 0.f);
            }
        }
        cpa_commit();
        for (int idx = tid; idx < tcr8 * RR; idx += 256) {
            int jj = idx >> 4, rb = idx & 15;
            float v = 0.f;
            if (jj < tc) {
                float dd = g_dist[r * NN + t0 + jj] - MUSTEP * (float)rb;
                v = __expf(-GAMMA * dd * dd);
            }
            rbfs[jj * RBs + rb] = v;
        }
        cpa_wait<0>();
        __syncthreads();

        // gemm1 (K=16): m1 = silu(base1 + t1 + rbf @ wrbf), in-place on m1s rows
        {
            const int jr = wq << 3;
            if (jr < tc) {
                const int c4 = lane * 4;
                float4 bb = *(const float4*)(base1 + c4);
                u64 acc[8][2];
#pragma unroll
                for (int jj = 0; jj < 8; jj++) {
                    float4 t = *(const float4*)(m1s + (jr + jj) * MSs + c4);
                    acc[jj][0] = pk2(bb.x + t.x, bb.y + t.y);
                    acc[jj][1] = pk2(bb.z + t.z, bb.w + t.w);
                }
#pragma unroll
                for (int k = 0; k < RR; k += 4) {
                    ulonglong2 w0 = *(const ulonglong2*)(wrbf + (k + 0) * HH + c4);
                    ulonglong2 w1 = *(const ulonglong2*)(wrbf + (k + 1) * HH + c4);
                    ulonglong2 w2 = *(const ulonglong2*)(wrbf + (k + 2) * HH + c4);
                    ulonglong2 w3 = *(const ulonglong2*)(wrbf + (k + 3) * HH + c4);
#pragma unroll
                    for (int jj = 0; jj < 8; jj++) {
                        float4 uv = *(const float4*)(rbfs + (jr + jj) * RBs + k);
                        u64 a0 = pk2(uv.x, uv.x), a1 = pk2(uv.y, uv.y);
                        u64 a2 = pk2(uv.z, uv.z), a3 = pk2(uv.w, uv.w);
                        acc[jj][0] = fma2(a0, w0.x, acc[jj][0]);
                        acc[jj][1] = fma2(a0, w0.y, acc[jj][1]);
                        acc[jj][0] = fma2(a1, w1.x, acc[jj][0]);
                        acc[jj][1] = fma2(a1, w1.y, acc[jj][1]);
                        acc[jj][0] = fma2(a2, w2.x, acc[jj][0]);
                        acc[jj][1] = fma2(a2, w2.y, acc[jj][1]);
                        acc[jj][0] = fma2(a3, w3.x, acc[jj][0]);
                        acc[jj][1] = fma2(a3, w3.y, acc[jj][1]);
                    }
                }
#pragma unroll
                for (int jj = 0; jj < 8; jj++) {
                    float2 t0v = upk(acc[jj][0]), t1v = upk(acc[jj][1]);
                    float4 o;
                    o.x = silu_f(t0v.x); o.y = silu_f(t0v.y);
                    o.z = silu_f(t1v.x); o.w = silu_f(t1v.y);
                    *(float4*)(m1s + (jr + jj) * MSs + c4) = o;
                }
            }
        }
        __syncthreads();

        gemmT<128>(m1s, MSs, wb2, eb2s, ms, MSs, tid, tc);     // m
        __syncthreads();

        {
            int q = tid >> 7, c = tid & 127;
            float s = 0.f;
            for (int jj = q; jj < tc; jj += 2) s += ms[jj * MSs + c];
            part2[q * 128 + c] = s;
        }
        __syncthreads();
        if (tid < HH) aggs[tid] += part2[tid] + part2[128 + tid];

        gemmT<128>(ms, MSs, wb3, cb1s, m1s, MSs, tid, tc);     // c1
        __syncthreads();

        {
            int e = tid >> 2, s4 = tid & 3;
            float s = 0.f;
            if (e < tc) {
                const float* mr = m1s + e * MSs + s4 * 32;
                const float* cw = cW2s + s4 * 32;
#pragma unroll
                for (int q = 0; q < 32; q++) s = fmaf(mr[q], cw[q], s);
            }
            s += __shfl_down_sync(0xffffffffu, s, 2, 4);
            s += __shfl_down_sync(0xffffffffu, s, 1, 4);
            if (s4 == 0) {
                if (e < tc) {
                    const float* dv = g_dvec + (size_t)(r * NN + t0 + e) * 3;
                    cont[e * 3 + 0] = dv[0] * s;
                    cont[e * 3 + 1] = dv[1] * s;
                    cont[e * 3 + 2] = dv[2] * s;
                } else {
                    cont[e * 3 + 0] = 0.f; cont[e * 3 + 1] = 0.f; cont[e * 3 + 2] = 0.f;
                }
            }
        }
        __syncthreads();
        if (tid < 3) {
            float a0 = 0.f, a1 = 0.f, a2 = 0.f, a3 = 0.f;
#pragma unroll
            for (int jj = 0; jj < TT; jj += 4) {
                a0 += cont[(jj + 0) * 3 + tid];
                a1 += cont[(jj + 1) * 3 + tid];
                a2 += cont[(jj + 2) * 3 + tid];
                a3 += cont[(jj + 3) * 3 + tid];
            }
            xacc[tid] += (a0 + a1) + (a2 + a3);
        }
        __syncthreads();
    }

    if (tid < HH) g_agg[r * HH + tid] = aggs[tid];
    if (tid < 3) {   // fused coordinate update (k_edge never reads g_x)
        float v = g_x[r * 3 + tid] + xacc[tid];
        g_x[r * 3 + tid] = v;
        if (last) out[r * 3 + tid] = v;
    }
}

// ---------------- launch ----------------
extern "C" void kernel_launch(void* const* d_in, const int* in_sizes, int n_in,
                              void* d_out, int out_size) {
    const float* z      = (const float*)d_in[0];
    const float* anchor = (const float*)d_in[1];
    const float* proj_W = (const float*)d_in[2];
    const float* proj_b = (const float*)d_in[3];
    const float* eW1    = (const float*)d_in[4];
    const float* eb1    = (const float*)d_in[5];
    const float* eW2    = (const float*)d_in[6];
    const float* eb2    = (const float*)d_in[7];
    const float* nW1    = (const float*)d_in[8];
    const float* nb1    = (const float*)d_in[9];
    const float* nW2    = (const float*)d_in[10];
    const float* nb2    = (const float*)d_in[11];
    const float* cW1    = (const float*)d_in[12];
    const float* cb1    = (const float*)d_in[13];
    const float* cW2    = (const float*)d_in[14];

    cudaFuncSetAttribute(k_edge, cudaFuncAttributeMaxDynamicSharedMemorySize, SMEM_EDGE);
    cudaFuncSetAttribute(k_prep, cudaFuncAttributeMaxDynamicSharedMemorySize, SB_PREP);

    k_init<<<NN + 1, 128>>>(z, proj_W, proj_b, anchor);
    for (int l = 0; l < LL; l++) {
        k_prep<<<NN + NN / RBB, 256, SB_PREP>>>(eW1, eb1, nW1, nb1, nW2, nb2, l, l > 0);
        if (l == 0) k_sched<<<1, NN>>>();
        k_edge<<<NN, 256, SMEM_EDGE>>>(eW1, eW2, eb2, cW1, cb1, cW2,
                                       (float*)d_out, l, l == LL - 1);
    }
}